// round 10
// baseline (speedup 1.0000x reference)
#include <cuda_runtime.h>
#include <cuda_fp16.h>
#include <mma.h>
#include <cstdint>

using namespace nvcuda;

// ---------------------------------------------------------------------------
// S4D kernel materialization via WMMA fp16 tensor cores (HMMA, sm_100-safe).
//   K[d,l] = 2*Re( sum_n Cc[d,n] * exp(dtA[d,n] * l) ),  D=512, N=32, L=8192
//
// Split l = 64*m + b:  K[d, 64m+b] = sum_k A[m,k]*B[b,k]  (real GEMM, K=64)
//   A[m, n]    = Re(u),  A[m, 32+n] = Im(u),  u = 2*Cc_n * exp(dtA_n*64m)
//   B[b, n]    = Re(w),  B[b, 32+n] = -Im(w), w = exp(dtA_n*b)
//
// Round 9 (re-bench; previous attempt hit an infra failure): 2 CTAs per d
// (M split in halves of 64 rows) -> 1024 CTAs, 26.5 KB smem,
// launch_bounds(128,7) -> 7 CTAs/SM = 28 warps/SM (occ ~44%) in a single
// wave, per-CTA critical path roughly halved. Only warp 3 runs the precise
// Cc discretization path.
// ---------------------------------------------------------------------------

#define D_MODEL 512
#define SEQ     8192
#define NST     32
#define LDAB    72                    // fp16 elems per A/B smem row (144 B)

// Dynamic smem layout (bytes)
#define OFF_A   0                     // 64 x 144 = 9216
#define OFF_B   9216                  // 64 x 144 = 9216
#define OFF_TR  18432                 // float2[16][34] = 4352
#define OFF_TQ  22784                 // float2[16][34] = 4352
#define TROW    34
#define SMEM_TOTAL 27136

// ---- helpers ---------------------------------------------------------------
__device__ __forceinline__ float2 cmul(float2 a, float2 b) {
    return make_float2(a.x * b.x - a.y * b.y, a.x * b.y + a.y * b.x);
}
// exp(scale*(dtAr + i*dtAi)), scale integer-valued up to 7680.
// Angle in fp64, reduced mod 2pi -> exact phase; fp32 fast sin/cos/exp.
__device__ __forceinline__ float2 cexp_int(float dtAr, float dtAi, float scale) {
    float e = __expf(scale * dtAr);
    double mi = (double)scale * (double)dtAi;
    double k  = rint(mi * 0.15915494309189535);
    float th  = (float)(mi - k * 6.283185307179586);
    float s, c;
    __sincosf(th, &s, &c);
    return make_float2(e * c, e * s);
}
// pack two fp32 -> half2 (v0 in low half = lower address)
__device__ __forceinline__ uint32_t pkh2(float v0, float v1) {
    __half2 h = __halves2half2(__float2half_rn(v0), __float2half_rn(v1));
    return *(uint32_t*)&h;
}

// ---------------------------------------------------------------------------
__global__ void __launch_bounds__(128, 7)
s4d_wmma_kernel(const float* __restrict__ log_dt,
                const float* __restrict__ log_A_real,
                const float* __restrict__ A_imag,
                const float2* __restrict__ C,
                float* __restrict__ out)
{
    extern __shared__ char dsm[];
    float2*   tR   = (float2*)(dsm + OFF_TR);   // 0-7: r^i ; 8-15: r^(8j)
    float2*   tQ   = (float2*)(dsm + OFF_TQ);   // 0-7: r^(64i) ; 8-15: Cc*r^(512*(8*mhalf+j))
    uint32_t* a32  = (uint32_t*)(dsm + OFF_A);  // 36 u32 per row
    uint32_t* b32  = (uint32_t*)(dsm + OFF_B);

    const int d     = blockIdx.x >> 1;
    const int mhalf = blockIdx.x & 1;
    const int tid   = threadIdx.x;
    const int wid   = tid >> 5;
    const int lane  = tid & 31;

    // ---- Phase 1: tables. Warp w builds 8 rows; only warp 3 needs Cc. ------
    {
        int i = d * NST + lane;
        float dt   = __expf(log_dt[d]);
        float dtAr = -expf(log_A_real[i]) * dt;
        float dtAi = A_imag[i] * dt;

        if (wid == 3) {
            // precise discretized C with the final 2x folded in
            float Ar = dtAr / dt;          // == -exp(log_A_real[i])
            float Ai = A_imag[i];
            float er = expf(dtAr);
            float s, c;
            sincosf(dtAi, &s, &c);
            float Er = er * c - 1.0f, Ei = er * s;
            float ar8 = Ar + 1e-8f;
            float inv = 1.0f / (ar8 * ar8 + Ai * Ai);
            float qr = (Er * ar8 + Ei * Ai) * inv;
            float qi = (Ei * ar8 - Er * Ai) * inv;
            float2 Cv = C[i];
            float2 Cc = make_float2(2.0f * (Cv.x * qr - Cv.y * qi),
                                    2.0f * (Cv.x * qi + Cv.y * qr));
#pragma unroll
            for (int j = 0; j < 8; j++) {
                float2 v = cexp_int(dtAr, dtAi, (float)(512 * (8 * mhalf + j)));
                tQ[(8 + j) * TROW + lane] = cmul(Cc, v);
            }
        } else if (wid == 0) {
#pragma unroll
            for (int j = 0; j < 8; j++)
                tR[j * TROW + lane] = cexp_int(dtAr, dtAi, (float)j);
        } else if (wid == 1) {
#pragma unroll
            for (int j = 0; j < 8; j++)
                tR[(8 + j) * TROW + lane] = cexp_int(dtAr, dtAi, (float)(8 * j));
        } else {
#pragma unroll
            for (int j = 0; j < 8; j++)
                tQ[j * TROW + lane] = cexp_int(dtAr, dtAi, (float)(64 * j));
        }
    }
    __syncthreads();

    // ---- Phase 2: operands. Thread: half A row + half B row (8 n2 each) ----
    {
        int row = tid >> 1;              // 0..63
        int h0  = (tid & 1) * 8;         // n2 offset

        // A local row m' = row (global m = 64*mhalf + m'):
        //   u = Q1[m'&7] * Q2loc[m'>>3]
        const float4* qa = (const float4*)(tQ + (row & 7) * TROW);
        const float4* qb = (const float4*)(tQ + (8 + (row >> 3)) * TROW);
#pragma unroll
        for (int k = 0; k < 8; k++) {
            int n2 = h0 + k;
            float4 a = qa[n2], q = qb[n2];
            float2 u0 = cmul(make_float2(a.x, a.y), make_float2(q.x, q.y));
            float2 u1 = cmul(make_float2(a.z, a.w), make_float2(q.z, q.w));
            a32[row * 36 + n2]      = pkh2(u0.x, u1.x);   // Re
            a32[row * 36 + 16 + n2] = pkh2(u0.y, u1.y);   // Im
        }

        // B row b = row: w = R1[b&7] * R2[b>>3]
        const float4* sa = (const float4*)(tR + (row & 7) * TROW);
        const float4* sb = (const float4*)(tR + (8 + (row >> 3)) * TROW);
#pragma unroll
        for (int k = 0; k < 8; k++) {
            int n2 = h0 + k;
            float4 a = sa[n2], q = sb[n2];
            float2 w0 = cmul(make_float2(a.x, a.y), make_float2(q.x, q.y));
            float2 w1 = cmul(make_float2(a.z, a.w), make_float2(q.z, q.w));
            b32[row * 36 + n2]      = pkh2(w0.x, w1.x);    // Re
            b32[row * 36 + 16 + n2] = pkh2(-w0.y, -w1.y);  // -Im
        }
    }
    __syncthreads();

    // ---- Phase 3: WMMA. Warp w: M-tile w (16 rows), N-tiles 0..3 ------------
    {
        const __half* Ah = (const __half*)(dsm + OFF_A);
        const __half* Bh = (const __half*)(dsm + OFF_B);

        wmma::fragment<wmma::accumulator, 16, 16, 16, float> acc[4];
#pragma unroll
        for (int j = 0; j < 4; j++) wmma::fill_fragment(acc[j], 0.0f);

#pragma unroll
        for (int k = 0; k < 4; k++) {
            wmma::fragment<wmma::matrix_a, 16, 16, 16, __half,
                           wmma::row_major> af;
            wmma::load_matrix_sync(af, Ah + wid * 16 * LDAB + k * 16, LDAB);
#pragma unroll
            for (int j = 0; j < 4; j++) {
                wmma::fragment<wmma::matrix_b, 16, 16, 16, __half,
                               wmma::col_major> bf;
                wmma::load_matrix_sync(bf, Bh + j * 16 * LDAB + k * 16, LDAB);
                wmma::mma_sync(acc[j], af, bf, acc[j]);
            }
        }

        // epilogue: D[m',b] -> out[d*8192 + (64*mhalf + m')*64 + b]
        float* od = out + (size_t)d * SEQ + (size_t)(64 * mhalf + wid * 16) * 64;
#pragma unroll
        for (int j = 0; j < 4; j++)
            wmma::store_matrix_sync(od + j * 16, acc[j], 64, wmma::mem_row_major);
    }
}

// ---------------------------------------------------------------------------
extern "C" void kernel_launch(void* const* d_in, const int* in_sizes, int n_in,
                              void* d_out, int out_size)
{
    const float*  log_dt     = (const float*)d_in[0];
    const float*  log_A_real = (const float*)d_in[1];
    const float*  A_imag     = (const float*)d_in[2];
    const float2* C          = (const float2*)d_in[3];
    float* out = (float*)d_out;

    static bool attr_set = false;
    if (!attr_set) {
        cudaFuncSetAttribute(s4d_wmma_kernel,
                             cudaFuncAttributeMaxDynamicSharedMemorySize,
                             SMEM_TOTAL);
        attr_set = true;
    }
    s4d_wmma_kernel<<<2 * D_MODEL, 128, SMEM_TOTAL>>>(
        log_dt, log_A_real, A_imag, C, out);
}

// round 11
// speedup vs baseline: 1.1734x; 1.1734x over previous
#include <cuda_runtime.h>
#include <cuda_fp16.h>
#include <mma.h>
#include <cstdint>

using namespace nvcuda;

// ---------------------------------------------------------------------------
// S4D kernel materialization via WMMA fp16 tensor cores (HMMA, sm_100-safe).
//   K[d,l] = 2*Re( sum_n Cc[d,n] * exp(dtA[d,n] * l) ),  D=512, N=32, L=8192
//
// Split l = 64*m + b (m in [0,128), b in [0,64)):
//   K[d, 64m+b] = sum_k A[m,k] * B[b,k]       (real GEMM, Kdim = 64)
//   A[m, n]    = Re(u),  A[m, 32+n] = Im(u),  u = 2*Cc_n * exp(dtA_n*64m)
//   B[b, n]    = Re(w),  B[b, 32+n] = -Im(w), w = exp(dtA_n*b)
//
// Round 11 = Round 8 structure minus ALL fp64 and ALL precise libm:
//   - fp32 Cody-Waite mod-2pi (validated in R7; phase err ~1.4e-4 rad max)
//   - Cc via fast intrinsics (dtAi <= 0.314 -> err ~1e-6), only in warps 2-3
// R10 showed fp64 angle math was ~40% of wall (18.4 cyc/warp-inst, SM-wide).
// ---------------------------------------------------------------------------

#define D_MODEL 512
#define SEQ     8192
#define NST     32
#define LDAB    72                    // fp16 elems per A/B smem row (144 B)

// Dynamic smem layout (bytes)
#define OFF_AH  0                     // 128 x 144 = 18432
#define OFF_BH  18432                 // 64 x 144  = 9216
#define OFF_TR  27648                 // float2[16][34] = 4352  (R tables)
#define OFF_TQ  32000                 // float2[24][34] = 6528  (Q tables)
#define TROW    34
#define SMEM_TOTAL 38528

// ---- helpers ---------------------------------------------------------------
__device__ __forceinline__ float2 cmul(float2 a, float2 b) {
    return make_float2(a.x * b.x - a.y * b.y, a.x * b.y + a.y * b.x);
}
// exp(scale*(dtAr + i*dtAi)), scale integer-valued up to 7680, all fp32.
// 2-term Cody-Waite mod-2pi; residual phase err ~1.4e-4 rad at max scale.
__device__ __forceinline__ float2 cexp_fast(float dtAr, float dtAi, float scale) {
    float e  = __expf(scale * dtAr);
    float mi = scale * dtAi;
    float k  = rintf(mi * 0.15915494f);
    float th = fmaf(-k, 6.2831855f, mi);     // 2pi hi
    th = fmaf(k, 1.7484556e-7f, th);         // 2pi lo correction
    float s, c;
    __sincosf(th, &s, &c);
    return make_float2(e * c, e * s);
}
// pack two fp32 -> half2 (v0 in low half = lower address)
__device__ __forceinline__ uint32_t pkh2(float v0, float v1) {
    __half2 h = __halves2half2(__float2half_rn(v0), __float2half_rn(v1));
    return *(uint32_t*)&h;
}

// ---------------------------------------------------------------------------
__global__ void __launch_bounds__(128, 4)
s4d_wmma_kernel(const float* __restrict__ log_dt,
                const float* __restrict__ log_A_real,
                const float* __restrict__ A_imag,
                const float2* __restrict__ C,
                float* __restrict__ out)
{
    extern __shared__ char dsm[];
    float2*   tR   = (float2*)(dsm + OFF_TR);   // rows 0-7: r^i ; 8-15: r^(8j)
    float2*   tQ   = (float2*)(dsm + OFF_TQ);   // rows 0-7: r^(64i); 8-23: Cc*r^(512j)
    uint32_t* ah32 = (uint32_t*)(dsm + OFF_AH); // 36 u32 per row
    uint32_t* bh32 = (uint32_t*)(dsm + OFF_BH);

    const int d    = blockIdx.x;
    const int tid  = threadIdx.x;
    const int wid  = tid >> 5;
    const int lane = tid & 31;

    // ---- Phase 1: all tables, direct fp32 exponentials, 10 rows per warp ---
    {
        int i = d * NST + lane;
        float dt   = __expf(log_dt[d]);
        float Ar   = -__expf(log_A_real[i]);
        float Ai   = A_imag[i];
        float dtAr = Ar * dt;
        float dtAi = Ai * dt;

        // Cc needed only for rows >= 24, i.e. warps 2 and 3.
        float2 Cc = make_float2(0.f, 0.f);
        if (wid >= 2) {
            float er = __expf(dtAr);
            float s, c;
            __sincosf(dtAi, &s, &c);             // |dtAi| <= 0.314: accurate
            float Er = er * c - 1.0f, Ei = er * s;
            float ar8 = Ar + 1e-8f;
            float inv = 1.0f / (ar8 * ar8 + Ai * Ai);
            float qr = (Er * ar8 + Ei * Ai) * inv;
            float qi = (Ei * ar8 - Er * Ai) * inv;
            float2 Cv = C[i];
            Cc = make_float2(2.0f * (Cv.x * qr - Cv.y * qi),
                             2.0f * (Cv.x * qi + Cv.y * qr));
        }

        // 40 logical rows: [0,8) R1=r^i ; [8,16) R2=r^(8j) ;
        //                  [16,24) Q1=r^(64i) ; [24,40) Q2=Cc*r^(512j)
#pragma unroll
        for (int rr = 0; rr < 10; rr++) {
            int rho = wid * 10 + rr;
            float scale;
            if      (rho < 8)  scale = (float)rho;
            else if (rho < 16) scale = (float)(8 * (rho - 8));
            else if (rho < 24) scale = (float)(64 * (rho - 16));
            else               scale = (float)(512 * (rho - 24));
            float2 v = cexp_fast(dtAr, dtAi, scale);
            if (rho >= 24) v = cmul(Cc, v);
            if (rho < 16) tR[rho * TROW + lane] = v;
            else          tQ[(rho - 16) * TROW + lane] = v;
        }
    }
    __syncthreads();

    // ---- Phase 2: operands (merged). Each thread: A row tid + half B row ---
    {
        // A row m = tid: u = Q1[m&7] * Q2[m>>3]
        int m = tid;
        const float4* ra = (const float4*)(tQ + (m & 7) * TROW);
        const float4* rb = (const float4*)(tQ + (8 + (m >> 3)) * TROW);
#pragma unroll
        for (int n2 = 0; n2 < 16; n2++) {
            float4 a = ra[n2], q = rb[n2];
            float2 u0 = cmul(make_float2(a.x, a.y), make_float2(q.x, q.y));
            float2 u1 = cmul(make_float2(a.z, a.w), make_float2(q.z, q.w));
            ah32[m * 36 + n2]      = pkh2(u0.x, u1.x);   // Re
            ah32[m * 36 + 16 + n2] = pkh2(u0.y, u1.y);   // Im
        }

        // Half B row: b = tid>>1, n2 in [8*(tid&1), +8): w = R1[b&7]*R2[b>>3]
        int b  = tid >> 1;
        int h0 = (tid & 1) * 8;
        const float4* sa = (const float4*)(tR + (b & 7) * TROW);
        const float4* sb = (const float4*)(tR + (8 + (b >> 3)) * TROW);
#pragma unroll
        for (int n2i = 0; n2i < 8; n2i++) {
            int n2 = h0 + n2i;
            float4 a = sa[n2], q = sb[n2];
            float2 w0 = cmul(make_float2(a.x, a.y), make_float2(q.x, q.y));
            float2 w1 = cmul(make_float2(a.z, a.w), make_float2(q.z, q.w));
            bh32[b * 36 + n2]      = pkh2(w0.x, w1.x);    // Re
            bh32[b * 36 + 16 + n2] = pkh2(-w0.y, -w1.y);  // -Im
        }
    }
    __syncthreads();

    // ---- Phase 3: WMMA single pass. Warp w: M-tiles {2w,2w+1} x N 0..3 ------
    {
        const __half* Ah = (const __half*)(dsm + OFF_AH);
        const __half* Bh = (const __half*)(dsm + OFF_BH);

        wmma::fragment<wmma::accumulator, 16, 16, 16, float> acc[2][4];
#pragma unroll
        for (int i = 0; i < 2; i++)
#pragma unroll
            for (int j = 0; j < 4; j++) wmma::fill_fragment(acc[i][j], 0.0f);

#pragma unroll
        for (int k = 0; k < 4; k++) {
            wmma::fragment<wmma::matrix_a, 16, 16, 16, __half,
                           wmma::row_major> af[2];
#pragma unroll
            for (int i = 0; i < 2; i++)
                wmma::load_matrix_sync(
                    af[i], Ah + (wid * 2 + i) * 16 * LDAB + k * 16, LDAB);
#pragma unroll
            for (int j = 0; j < 4; j++) {
                wmma::fragment<wmma::matrix_b, 16, 16, 16, __half,
                               wmma::col_major> bf;
                wmma::load_matrix_sync(bf, Bh + j * 16 * LDAB + k * 16, LDAB);
                wmma::mma_sync(acc[0][j], af[0], bf, acc[0][j]);
                wmma::mma_sync(acc[1][j], af[1], bf, acc[1][j]);
            }
        }

        // ---- epilogue: D[m,b] -> out[d*8192 + m*64 + b] --------------------
        float* od = out + (size_t)d * SEQ;
#pragma unroll
        for (int i = 0; i < 2; i++)
#pragma unroll
            for (int j = 0; j < 4; j++)
                wmma::store_matrix_sync(
                    od + (wid * 2 + i) * 16 * 64 + j * 16, acc[i][j], 64,
                    wmma::mem_row_major);
    }
}

// ---------------------------------------------------------------------------
extern "C" void kernel_launch(void* const* d_in, const int* in_sizes, int n_in,
                              void* d_out, int out_size)
{
    const float*  log_dt     = (const float*)d_in[0];
    const float*  log_A_real = (const float*)d_in[1];
    const float*  A_imag     = (const float*)d_in[2];
    const float2* C          = (const float2*)d_in[3];
    float* out = (float*)d_out;

    static bool attr_set = false;
    if (!attr_set) {
        cudaFuncSetAttribute(s4d_wmma_kernel,
                             cudaFuncAttributeMaxDynamicSharedMemorySize,
                             SMEM_TOTAL);
        attr_set = true;
    }
    s4d_wmma_kernel<<<D_MODEL, 128, SMEM_TOTAL>>>(
        log_dt, log_A_real, A_imag, C, out);
}

// round 12
// speedup vs baseline: 1.4369x; 1.2246x over previous
#include <cuda_runtime.h>
#include <cuda_fp16.h>
#include <cstdint>

// ---------------------------------------------------------------------------
// S4D kernel materialization via raw mma.sync (HMMA.16816), sm_100-safe.
//   K[d,l] = 2*Re( sum_n Cc[d,n] * exp(dtA[d,n] * l) ),  D=512, N=32, L=8192
//
// Split l = 64*m + b:  K[d,64m+b] = sum_k A[m,k]*B[b,k]  (real GEMM, K=64)
//   A[m, n] = Re(u), A[m,32+n] = Im(u),  u = 2*Cc_n * exp(dtA_n*64m)
//   B[b, n] = Re(w), B[b,32+n] = -Im(w), w = exp(dtA_n*b)
//
// Round 12: A fragments built DIRECTLY in registers (no smem, no barrier,
// no ldmatrix — warp w's MMA consumes only warp-w-computed rows). B built
// once in smem (shared by all warps) via slim r-power tables, consumed with
// conflict-free LDS.32 into b-fragments. Phases: tables -> bar -> B -> bar
// -> straight-line A-build + MMA + store.
// ---------------------------------------------------------------------------

#define D_MODEL 512
#define SEQ     8192
#define NST     32
#define TROW    34                    // float2 per table row (pad)
#define BROW32  36                    // u32 per B row (72 halves = 144 B)

// ---- helpers ---------------------------------------------------------------
__device__ __forceinline__ float2 cmul(float2 a, float2 b) {
    return make_float2(a.x * b.x - a.y * b.y, a.x * b.y + a.y * b.x);
}
// exp(scale*(dtAr + i*dtAi)), fp32 Cody-Waite mod-2pi (validated R7/R11).
__device__ __forceinline__ float2 cexp_fast(float dtAr, float dtAi, float scale) {
    float e  = __expf(scale * dtAr);
    float mi = scale * dtAi;
    float k  = rintf(mi * 0.15915494f);
    float th = fmaf(-k, 6.2831855f, mi);
    th = fmaf(k, 1.7484556e-7f, th);
    float s, c;
    __sincosf(th, &s, &c);
    return make_float2(e * c, e * s);
}
// pack two fp32 -> half2 (v0 in low half)
__device__ __forceinline__ uint32_t pkh2(float v0, float v1) {
    __half2 h = __halves2half2(__float2half_rn(v0), __float2half_rn(v1));
    return *(uint32_t*)&h;
}
__device__ __forceinline__ void mma16816(float* acc, const uint32_t* a,
                                         const uint32_t* b) {
    asm volatile(
        "mma.sync.aligned.m16n8k16.row.col.f32.f16.f16.f32 "
        "{%0,%1,%2,%3}, {%4,%5,%6,%7}, {%8,%9}, {%0,%1,%2,%3};"
        : "+f"(acc[0]), "+f"(acc[1]), "+f"(acc[2]), "+f"(acc[3])
        : "r"(a[0]), "r"(a[1]), "r"(a[2]), "r"(a[3]), "r"(b[0]), "r"(b[1]));
}

// ---------------------------------------------------------------------------
__global__ void __launch_bounds__(128, 4)
s4d_mma_kernel(const float* __restrict__ log_dt,
               const float* __restrict__ log_A_real,
               const float* __restrict__ A_imag,
               const float2* __restrict__ C,
               float* __restrict__ out)
{
    __shared__ float2   tR[16 * TROW];        // rows 0-7: r^i ; 8-15: r^(8j)
    __shared__ uint32_t Bs[64 * BROW32];      // B fp16 [b][72 halves]

    const int d   = blockIdx.x;
    const int tid = threadIdx.x;
    const int w   = tid >> 5;
    const int l   = tid & 31;
    const int q   = l & 3;
    const int g   = l >> 2;

    // ---- per-lane-n constants (lane l owns state n = l) --------------------
    int i = d * NST + l;
    float dt   = __expf(log_dt[d]);
    float Ar   = -__expf(log_A_real[i]);
    float Ai   = A_imag[i];
    float dtAr = Ar * dt;
    float dtAi = Ai * dt;

    // discretized C with final 2x folded in (fast intrinsics; |dtAi|<=0.314)
    float er = __expf(dtAr);
    float sn, cs;
    __sincosf(dtAi, &sn, &cs);
    float Er = er * cs - 1.0f, Ei = er * sn;
    float ar8 = Ar + 1e-8f;
    float inv = 1.0f / (ar8 * ar8 + Ai * Ai);
    float qr = (Er * ar8 + Ei * Ai) * inv;
    float qi = (Ei * ar8 - Er * Ai) * inv;
    float2 Cv = C[i];
    float Ccr = 2.0f * (Cv.x * qr - Cv.y * qi);
    float Cci = 2.0f * (Cv.x * qi + Cv.y * qr);
    float2 r512 = cexp_fast(dtAr, dtAi, 512.0f);

    // ---- Phase 1: tR tables (16 rows; warp w builds rows 4w..4w+3) ---------
#pragma unroll
    for (int rr = 0; rr < 4; rr++) {
        int row = 4 * w + rr;
        float scale = (row < 8) ? (float)row : (float)(8 * (row - 8));
        tR[row * TROW + l] = cexp_fast(dtAr, dtAi, scale);
    }
    __syncthreads();

    // ---- Phase 2: B in smem (b = tid>>1, 8 n2-units each) ------------------
    {
        int b  = tid >> 1;
        int h0 = (tid & 1) * 8;
        const float4* sa = (const float4*)(tR + (b & 7) * TROW);
        const float4* sb = (const float4*)(tR + (8 + (b >> 3)) * TROW);
#pragma unroll
        for (int n2i = 0; n2i < 8; n2i++) {
            int n2 = h0 + n2i;
            float4 a = sa[n2], p = sb[n2];
            float2 w0 = cmul(make_float2(a.x, a.y), make_float2(p.x, p.y));
            float2 w1 = cmul(make_float2(a.z, a.w), make_float2(p.z, p.w));
            Bs[b * BROW32 + n2]      = pkh2(w0.x, w1.x);    // Re  (k = 2n2,2n2+1)
            Bs[b * BROW32 + 16 + n2] = pkh2(-w0.y, -w1.y);  // -Im (k = 32+2n2,..)
        }
    }

    // ---- Phase 3 (overlapped with B wait): A fragments in registers --------
    // Thread holds A elements: rows {32w+g, +8, +16, +24}, k-cols
    // {2q,2q+1,2q+8,2q+9}+16s  ->  n-set {2q,2q+1,2q+8,2q+9,+16 each}.
    uint32_t Afr[2][4][4];                   // [mtile][kstep][reg]
    const int m1 = 32 * w + g;
    const float fm = (float)(64 * m1);
#pragma unroll
    for (int p = 0; p < 4; p++) {
        int n0 = 2 * q + 8 * (p & 1) + 16 * (p >> 1);
        float uRe[2][4], uIm[2][4];
#pragma unroll
        for (int e = 0; e < 2; e++) {
            int nn = n0 + e;
            float dar = __shfl_sync(0xffffffffu, dtAr, nn);
            float dai = __shfl_sync(0xffffffffu, dtAi, nn);
            float ccr = __shfl_sync(0xffffffffu, Ccr, nn);
            float cci = __shfl_sync(0xffffffffu, Cci, nn);
            float r5r = __shfl_sync(0xffffffffu, r512.x, nn);
            float r5i = __shfl_sync(0xffffffffu, r512.y, nn);
            float2 x  = cexp_fast(dar, dai, fm);            // r^(64*m1)
            float2 u1 = cmul(make_float2(ccr, cci), x);     // m1
            float2 r5 = make_float2(r5r, r5i);
            float2 u2 = cmul(u1, r5);                       // m1+8
            float2 u3 = cmul(u2, r5);                       // m1+16
            float2 u4 = cmul(u3, r5);                       // m1+24
            uRe[e][0] = u1.x; uIm[e][0] = u1.y;
            uRe[e][1] = u2.x; uIm[e][1] = u2.y;
            uRe[e][2] = u3.x; uIm[e][2] = u3.y;
            uRe[e][3] = u4.x; uIm[e][3] = u4.y;
        }
        int s_re = p >> 1;          // kstep for Re (s=0,1); Im at s_re+2
        int ab   = 2 * (p & 1);     // reg pair offset (a0/a1 vs a2/a3)
        // mt0 rows: g -> u[.][0], g+8 -> u[.][1]; mt1: u[.][2], u[.][3]
        Afr[0][s_re][ab + 0]     = pkh2(uRe[0][0], uRe[1][0]);
        Afr[0][s_re][ab + 1]     = pkh2(uRe[0][1], uRe[1][1]);
        Afr[1][s_re][ab + 0]     = pkh2(uRe[0][2], uRe[1][2]);
        Afr[1][s_re][ab + 1]     = pkh2(uRe[0][3], uRe[1][3]);
        Afr[0][s_re + 2][ab + 0] = pkh2(uIm[0][0], uIm[1][0]);
        Afr[0][s_re + 2][ab + 1] = pkh2(uIm[0][1], uIm[1][1]);
        Afr[1][s_re + 2][ab + 0] = pkh2(uIm[0][2], uIm[1][2]);
        Afr[1][s_re + 2][ab + 1] = pkh2(uIm[0][3], uIm[1][3]);
    }
    __syncthreads();                 // B ready

    // ---- Phase 4: MMA + store, barrier-free --------------------------------
    // b-fragment (col-major 16x8): b0 = B[8bt+g][16s+2q..+1], b1 = +8.
    // LDS word = 36*(8bt+g) + 8s + q  ->  bank (4g+q+8s) % 32: conflict-free.
    float* od0 = out + (size_t)d * SEQ + (size_t)(32 * w + g) * 64 + 2 * q;
#pragma unroll
    for (int bt = 0; bt < 8; bt++) {
        uint32_t Bfr[4][2];
#pragma unroll
        for (int s = 0; s < 4; s++) {
            const uint32_t* brow = Bs + (8 * bt + g) * BROW32 + 8 * s + q;
            Bfr[s][0] = brow[0];
            Bfr[s][1] = brow[4];
        }
#pragma unroll
        for (int mt = 0; mt < 2; mt++) {
            float acc[4] = {0.f, 0.f, 0.f, 0.f};
#pragma unroll
            for (int s = 0; s < 4; s++) mma16816(acc, Afr[mt][s], Bfr[s]);
            // c0,c1 -> (row 32w+16mt+g, cols 8bt+2q,+1); c2,c3 -> row +8
            float* o = od0 + mt * 16 * 64 + 8 * bt;
            *(float2*)(o)            = make_float2(acc[0], acc[1]);
            *(float2*)(o + 8 * 64)   = make_float2(acc[2], acc[3]);
        }
    }
}

// ---------------------------------------------------------------------------
extern "C" void kernel_launch(void* const* d_in, const int* in_sizes, int n_in,
                              void* d_out, int out_size)
{
    const float*  log_dt     = (const float*)d_in[0];
    const float*  log_A_real = (const float*)d_in[1];
    const float*  A_imag     = (const float*)d_in[2];
    const float2* C          = (const float2*)d_in[3];
    float* out = (float*)d_out;

    s4d_mma_kernel<<<D_MODEL, 128>>>(log_dt, log_A_real, A_imag, C, out);
}